// round 3
// baseline (speedup 1.0000x reference)
#include <cuda_runtime.h>

// ---------------- problem constants ----------------
#define L_   8
#define H_   256
#define W_   448
#define KL_  2
#define KH_  18
#define KW_  32
#define K_   1152              // KL*KH*KW
#define HW_  (H_*W_)           // 114688
#define NPIX (L_*HW_)          // 917504
#define CMAX 840               // max pixels per cell: 4 * 15 * 14
#define SP_  848               // padded pixel stride for SMEM assoc matrix

#define T_SCALE   0.625f                       // Kl/(0.4*L)
#define YX_SCALE  ((float)0.17857142857142858) // max(Kh/(0.4*H), Kw/(0.4*W))
#define LAB_SCALE 0.26f

#define EM_THREADS 512
#define EM_SMEM    (27 * SP_ * (int)sizeof(float))   // 91584 bytes

// ---------------- device scratch (no allocs allowed) ----------------
__device__ float g_pF[K_*6*CMAX];   // cell-blocked pixel features [k][c][p] (~23MB)
__device__ float g_spFeat[K_*6];    // superpixel features [k][c]
__device__ float g_part[K_*189];    // per-block partial sums [k][j*7+c] (c=6 -> weight)

__device__ __forceinline__ float warpSum(float v){
#pragma unroll
    for (int o = 16; o > 0; o >>= 1) v += __shfl_down_sync(0xffffffffu, v, o);
    return v;
}

// cell geometry: t in [4kl,4kl+4), y in [y0,y0+ch), x in [14kw,14kw+14)
__device__ __forceinline__ void cellGeom(int k, int& kl, int& kh, int& kw, int& y0, int& ch){
    kl = k / (KH_*KW_);
    kh = (k / KW_) % KH_;
    kw = k % KW_;
    y0 = (256*kh + 17) / 18;
    int y1 = (256*(kh+1) + 17) / 18;
    ch = y1 - y0;  // 14 or 15
}

// ---------------- kernel 1: pFeat + blocked copy + sp_init mean ----------------
__global__ void __launch_bounds__(256) pa_kernel(const float* __restrict__ lab,
                                                 float* __restrict__ outPF){
    int k = blockIdx.x, tid = threadIdx.x;
    int kl, kh, kw, y0, ch;
    cellGeom(k, kl, kh, kw, y0, ch);
    int P = 56 * ch;  // 4 * ch * 14

    float s0=0.f,s1=0.f,s2=0.f,s3=0.f,s4=0.f,s5=0.f;
    float* gp = &g_pF[(size_t)k*6*CMAX];
#pragma unroll 1
    for (int p = tid; p < P; p += 256){
        int lx = p % 14, q = p / 14, ly = q % ch, lt = q / ch;
        int t = 4*kl + lt, y = y0 + ly, x = 14*kw + lx;
        int pix = t*HW_ + y*W_ + x;
        float f0 = T_SCALE  * (float)t;
        float f1 = YX_SCALE * (float)y;
        float f2 = YX_SCALE * (float)x;
        float f3 = LAB_SCALE * lab[pix];
        float f4 = LAB_SCALE * lab[NPIX + pix];
        float f5 = LAB_SCALE * lab[2*NPIX + pix];
        outPF[pix]          = f0;
        outPF[NPIX+pix]     = f1;
        outPF[2*NPIX+pix]   = f2;
        outPF[3*NPIX+pix]   = f3;
        outPF[4*NPIX+pix]   = f4;
        outPF[5*NPIX+pix]   = f5;
        gp[p]          = f0;
        gp[CMAX+p]     = f1;
        gp[2*CMAX+p]   = f2;
        gp[3*CMAX+p]   = f3;
        gp[4*CMAX+p]   = f4;
        gp[5*CMAX+p]   = f5;
        s0+=f0; s1+=f1; s2+=f2; s3+=f3; s4+=f4; s5+=f5;
    }
    __shared__ float red[6][8];
    int wid = tid >> 5, lane = tid & 31;
    float sv[6] = {s0,s1,s2,s3,s4,s5};
#pragma unroll
    for (int c = 0; c < 6; c++){
        float v = warpSum(sv[c]);
        if (lane == 0) red[c][wid] = v;
    }
    __syncthreads();
    if (tid < 6){
        float v = 0.f;
#pragma unroll
        for (int w = 0; w < 8; w++) v += red[tid][w];
        g_spFeat[k*6 + tid] = v / (float)P;
    }
}

// ---------------- kernel 2: two-phase fused assoc + accumulate ----------------
// Phase A: per-pixel softmax assoc -> SMEM matrix sA[27][SP_]
// Phase B: warp-per-channel coalesced dot products -> g_part (deterministic)
__global__ void __launch_bounds__(EM_THREADS, 2) em_kernel(){
    extern __shared__ float sA[];   // [27][SP_]
    int k = blockIdx.x, tid = threadIdx.x;
    int kl, kh, kw, y0, ch;
    cellGeom(k, kl, kh, kw, y0, ch);
    int P = 56 * ch;

    __shared__ float sSp[27][6];
    if (tid < 27){
        int dl = tid/9 - 1, dh = (tid/3)%3 - 1, dw = tid%3 - 1;
        int nl = min(max(kl+dl, 0), KL_-1);
        int nh = min(max(kh+dh, 0), KH_-1);
        int nw = min(max(kw+dw, 0), KW_-1);
        int nk = (nl*KH_ + nh)*KW_ + nw;
#pragma unroll
        for (int c = 0; c < 6; c++) sSp[tid][c] = g_spFeat[nk*6 + c];
    }
    unsigned vmask = 0;
#pragma unroll
    for (int j = 0; j < 27; j++){
        int dl = j/9 - 1, dh = (j/3)%3 - 1, dw = j%3 - 1;
        if ((unsigned)(kl+dl) < (unsigned)KL_ &&
            (unsigned)(kh+dh) < (unsigned)KH_ &&
            (unsigned)(kw+dw) < (unsigned)KW_) vmask |= (1u << j);
    }
    __syncthreads();

    const float* gp = &g_pF[(size_t)k*6*CMAX];

    // ---- Phase A ----
#pragma unroll 1
    for (int p = tid; p < P; p += EM_THREADS){
        float f0 = gp[p],        f1 = gp[CMAX+p],   f2 = gp[2*CMAX+p];
        float f3 = gp[3*CMAX+p], f4 = gp[4*CMAX+p], f5 = gp[5*CMAX+p];
        float e[27];
#pragma unroll
        for (int j = 0; j < 27; j++){
            float t0 = f0 - sSp[j][0]; float dd = t0*t0;
            t0 = f1 - sSp[j][1]; dd += t0*t0;
            t0 = f2 - sSp[j][2]; dd += t0*t0;
            t0 = f3 - sSp[j][3]; dd += t0*t0;
            t0 = f4 - sSp[j][4]; dd += t0*t0;
            t0 = f5 - sSp[j][5]; dd += t0*t0;
            e[j] = (vmask & (1u << j)) ? dd : 1e30f;
        }
        float m = e[0];
#pragma unroll
        for (int j = 1; j < 27; j++) m = fminf(m, e[j]);
        float sum = 0.f;
#pragma unroll
        for (int j = 0; j < 27; j++){ e[j] = __expf(m - e[j]); sum += e[j]; }
        float r = 1.0f / sum;
#pragma unroll
        for (int j = 0; j < 27; j++) sA[j*SP_ + p] = e[j] * r;
    }
    __syncthreads();

    // ---- Phase B: 189 channels (j,c), c==6 -> weight sum ----
    int wid = tid >> 5, lane = tid & 31;
#pragma unroll 1
    for (int chn = wid; chn < 189; chn += EM_THREADS/32){
        int j = chn / 7, c = chn - j*7;
        const float* aRow = &sA[j*SP_];
        float acc = 0.f;
        if (c < 6){
            const float* fRow = &gp[c*CMAX];
#pragma unroll 1
            for (int p = lane; p < P; p += 32) acc += aRow[p] * fRow[p];
        } else {
#pragma unroll 1
            for (int p = lane; p < P; p += 32) acc += aRow[p];
        }
        acc = warpSum(acc);
        if (lane == 0) g_part[k*189 + chn] = acc;
    }
}

// ---------------- kernel 3: gather partials -> normalized spFeat ----------------
__global__ void norm_kernel(){
    int k = blockIdx.x, lane = threadIdx.x;  // 32 threads, lanes 0..6 used
    int kl, kh, kw, y0, ch;
    cellGeom(k, kl, kh, kw, y0, ch);
    float v = 0.f;
    if (lane < 7){
#pragma unroll
        for (int j = 0; j < 27; j++){
            int dl = j/9 - 1, dh = (j/3)%3 - 1, dw = j%3 - 1;
            int bl = kl - dl, bh = kh - dh, bw = kw - dw;
            if ((unsigned)bl < (unsigned)KL_ &&
                (unsigned)bh < (unsigned)KH_ &&
                (unsigned)bw < (unsigned)KW_){
                int b = (bl*KH_ + bh)*KW_ + bw;
                v += g_part[b*189 + j*7 + lane];
            }
        }
    }
    float w = __shfl_sync(0xffffffffu, v, 6);
    if (lane < 6) g_spFeat[k*6 + lane] = v / fmaxf(w, 1e-12f);
}

// ---------------- kernel 4: final assoc + argmax + outputs ----------------
__global__ void __launch_bounds__(256) final_kernel(float* __restrict__ outA,
                                                    float* __restrict__ outF){
    int k = blockIdx.x, tid = threadIdx.x;
    int kl, kh, kw, y0, ch;
    cellGeom(k, kl, kh, kw, y0, ch);
    int P = 56 * ch;

    __shared__ float sSp[27][6];
    __shared__ int   sNk[27];
    if (tid < 27){
        int dl = tid/9 - 1, dh = (tid/3)%3 - 1, dw = tid%3 - 1;
        int nl = min(max(kl+dl, 0), KL_-1);
        int nh = min(max(kh+dh, 0), KH_-1);
        int nw = min(max(kw+dw, 0), KW_-1);
        int nk = (nl*KH_ + nh)*KW_ + nw;
        sNk[tid] = nk;
#pragma unroll
        for (int c = 0; c < 6; c++) sSp[tid][c] = g_spFeat[nk*6 + c];
    }
    unsigned vmask = 0;
#pragma unroll
    for (int j = 0; j < 27; j++){
        int dl = j/9 - 1, dh = (j/3)%3 - 1, dw = j%3 - 1;
        if ((unsigned)(kl+dl) < (unsigned)KL_ &&
            (unsigned)(kh+dh) < (unsigned)KH_ &&
            (unsigned)(kw+dw) < (unsigned)KW_) vmask |= (1u << j);
    }
    __syncthreads();

    const float* gp = &g_pF[(size_t)k*6*CMAX];
#pragma unroll 1
    for (int p = tid; p < P; p += 256){
        int lx = p % 14, q = p / 14, ly = q % ch, lt = q / ch;
        int t = 4*kl + lt, y = y0 + ly, x = 14*kw + lx;
        int pix = t*HW_ + y*W_ + x;

        float f0 = gp[p],        f1 = gp[CMAX+p],   f2 = gp[2*CMAX+p];
        float f3 = gp[3*CMAX+p], f4 = gp[4*CMAX+p], f5 = gp[5*CMAX+p];
        float e[27];
#pragma unroll
        for (int j = 0; j < 27; j++){
            float t0 = f0 - sSp[j][0]; float dd = t0*t0;
            t0 = f1 - sSp[j][1]; dd += t0*t0;
            t0 = f2 - sSp[j][2]; dd += t0*t0;
            t0 = f3 - sSp[j][3]; dd += t0*t0;
            t0 = f4 - sSp[j][4]; dd += t0*t0;
            t0 = f5 - sSp[j][5]; dd += t0*t0;
            e[j] = (vmask & (1u << j)) ? dd : 1e30f;
        }
        float m = e[0];
#pragma unroll
        for (int j = 1; j < 27; j++) m = fminf(m, e[j]);
        float sum = 0.f;
#pragma unroll
        for (int j = 0; j < 27; j++){ e[j] = __expf(m - e[j]); sum += e[j]; }
        float r = 1.0f / sum;

        float best = -1.f; int bj = 0;
#pragma unroll
        for (int j = 0; j < 27; j++){
            float a = e[j] * r;
            outA[(size_t)j*NPIX + pix] = a;
            if (a > best){ best = a; bj = j; }
        }
        outF[pix] = (float)sNk[bj];
    }
}

// ---------------- kernel 5: spFeat output (transposed to [c][k]) ----------------
__global__ void spout_kernel(float* __restrict__ outSP){
    int i = blockIdx.x * blockDim.x + threadIdx.x;
    if (i < 6*K_){
        int c = i / K_, k = i - c*K_;
        outSP[i] = g_spFeat[k*6 + c];
    }
}

// ---------------- launcher ----------------
extern "C" void kernel_launch(void* const* d_in, const int* in_sizes, int n_in,
                              void* d_out, int out_size){
    const float* lab = (const float*)d_in[0];
    if (n_in > 1 && in_sizes[0] != 3*NPIX) lab = (const float*)d_in[1];

    float* out   = (float*)d_out;
    float* outPF = out;                          // 6*N   = 5505024
    float* outSP = out + (size_t)6*NPIX;         // 6*K   = 6912
    float* outA  = outSP + 6*K_;                 // 27*N  = 24772608
    float* outF  = outA + (size_t)27*NPIX;       // N     = 917504

    cudaFuncSetAttribute(em_kernel, cudaFuncAttributeMaxDynamicSharedMemorySize, EM_SMEM);

    pa_kernel<<<K_, 256>>>(lab, outPF);
    for (int it = 0; it < 4; it++){
        em_kernel<<<K_, EM_THREADS, EM_SMEM>>>();
        norm_kernel<<<K_, 32>>>();
    }
    final_kernel<<<K_, 256>>>(outA, outF);
    spout_kernel<<<27, 256>>>(outSP);            // 6912 = 27*256
}

// round 4
// speedup vs baseline: 1.1888x; 1.1888x over previous
#include <cuda_runtime.h>

// ---------------- problem constants ----------------
#define L_   8
#define H_   256
#define W_   448
#define KL_  2
#define KH_  18
#define KW_  32
#define K_   1152              // KL*KH*KW
#define HW_  (H_*W_)           // 114688
#define NPIX (L_*HW_)          // 917504
#define CMAX 840               // max pixels per cell: 4 * 15 * 14
#define SP_  848               // padded pixel stride for SMEM assoc matrix

#define T_SCALE   0.625f                       // Kl/(0.4*L)
#define YX_SCALE  ((float)0.17857142857142858) // max(Kh/(0.4*H), Kw/(0.4*W))
#define LAB_SCALE 0.26f

#define EM_THREADS 512
#define EM_SMEM    (27 * SP_ * (int)sizeof(float))   // 91584 bytes dynamic

// ---------------- device scratch (no allocs allowed) ----------------
__device__ float g_pF[K_*6*CMAX];   // cell-blocked pixel features [k][c][p] (~23MB)
__device__ float g_spFeat[K_*6];    // superpixel features [k][c]
__device__ float g_part[K_*189];    // per-block partial sums [k][j*7+c] (c=6 -> weight)

__device__ __forceinline__ float warpSum(float v){
#pragma unroll
    for (int o = 16; o > 0; o >>= 1) v += __shfl_down_sync(0xffffffffu, v, o);
    return v;
}

// fast exp for u <= 0, FMA-pipe only (no MUFU). rel err ~2.4e-6.
__device__ __forceinline__ float fastExpNeg(float u){
    float y = fmaxf(u * 1.44269504f, -126.0f);
    float r = rintf(y);
    float f = y - r;
    float p = 1.33336498e-3f;
    p = fmaf(p, f, 9.61817007e-3f);
    p = fmaf(p, f, 5.55041087e-2f);
    p = fmaf(p, f, 2.40226507e-1f);
    p = fmaf(p, f, 6.93147182e-1f);
    p = fmaf(p, f, 1.0f);
    int n = (int)r;
    return p * __int_as_float((n + 127) << 23);
}

// cell geometry: t in [4kl,4kl+4), y in [y0,y0+ch), x in [14kw,14kw+14)
__device__ __forceinline__ void cellGeom(int k, int& kl, int& kh, int& kw, int& y0, int& ch){
    kl = k / (KH_*KW_);
    kh = (k / KW_) % KH_;
    kw = k % KW_;
    y0 = (256*kh + 17) / 18;
    int y1 = (256*(kh+1) + 17) / 18;
    ch = y1 - y0;  // 14 or 15
}

// fill sB[27][8]: [0..5] = -2*sp_c, [6] = |sp|^2, [7] pad. tid<27 threads.
__device__ __forceinline__ void fillNbr(int tid, int kl, int kh, int kw, float* sB, int* sNk){
    if (tid < 27){
        int dl = tid/9 - 1, dh = (tid/3)%3 - 1, dw = tid%3 - 1;
        int nl = min(max(kl+dl, 0), KL_-1);
        int nh = min(max(kh+dh, 0), KH_-1);
        int nw = min(max(kw+dw, 0), KW_-1);
        int nk = (nl*KH_ + nh)*KW_ + nw;
        if (sNk) sNk[tid] = nk;
        float b = 0.f;
#pragma unroll
        for (int c = 0; c < 6; c++){
            float s = g_spFeat[nk*6 + c];
            sB[tid*8 + c] = -2.0f * s;
            b = fmaf(s, s, b);
        }
        sB[tid*8 + 6] = b;
        sB[tid*8 + 7] = 0.f;
    }
}

__device__ __forceinline__ unsigned validMask(int kl, int kh, int kw){
    unsigned vmask = 0;
#pragma unroll
    for (int j = 0; j < 27; j++){
        int dl = j/9 - 1, dh = (j/3)%3 - 1, dw = j%3 - 1;
        if ((unsigned)(kl+dl) < (unsigned)KL_ &&
            (unsigned)(kh+dh) < (unsigned)KH_ &&
            (unsigned)(kw+dw) < (unsigned)KW_) vmask |= (1u << j);
    }
    return vmask;
}

// compute softmax assoc a[27] for one pixel from features f[6]
__device__ __forceinline__ void pixelAssoc(const float* __restrict__ sB, unsigned vmask,
                                           float f0, float f1, float f2,
                                           float f3, float f4, float f5, float* a){
    float e[27];
#pragma unroll
    for (int j = 0; j < 27; j++){
        float4 b0 = *(const float4*)&sB[j*8];
        float4 b1 = *(const float4*)&sB[j*8 + 4];
        float dd = b1.z;                 // |sp|^2
        dd = fmaf(f0, b0.x, dd);
        dd = fmaf(f1, b0.y, dd);
        dd = fmaf(f2, b0.z, dd);
        dd = fmaf(f3, b0.w, dd);
        dd = fmaf(f4, b1.x, dd);
        dd = fmaf(f5, b1.y, dd);
        e[j] = (vmask & (1u << j)) ? dd : 1e30f;
    }
    float m = e[0];
#pragma unroll
    for (int j = 1; j < 27; j++) m = fminf(m, e[j]);
    float sum = 0.f;
#pragma unroll
    for (int j = 0; j < 27; j++){
        float v = fastExpNeg(m - e[j]);
        v = (vmask & (1u << j)) ? v : 0.0f;
        a[j] = v; sum += v;
    }
    float r = 1.0f / sum;
#pragma unroll
    for (int j = 0; j < 27; j++) a[j] *= r;
}

// ---------------- kernel 1: pFeat + blocked copy + sp_init mean ----------------
__global__ void __launch_bounds__(256) pa_kernel(const float* __restrict__ lab,
                                                 float* __restrict__ outPF){
    int k = blockIdx.x, tid = threadIdx.x;
    int kl, kh, kw, y0, ch;
    cellGeom(k, kl, kh, kw, y0, ch);
    int P = 56 * ch;  // 4 * ch * 14

    float s0=0.f,s1=0.f,s2=0.f,s3=0.f,s4=0.f,s5=0.f;
    float* gp = &g_pF[(size_t)k*6*CMAX];
#pragma unroll 1
    for (int p = tid; p < P; p += 256){
        int lx = p % 14, q = p / 14, ly = q % ch, lt = q / ch;
        int t = 4*kl + lt, y = y0 + ly, x = 14*kw + lx;
        int pix = t*HW_ + y*W_ + x;
        float f0 = T_SCALE  * (float)t;
        float f1 = YX_SCALE * (float)y;
        float f2 = YX_SCALE * (float)x;
        float f3 = LAB_SCALE * lab[pix];
        float f4 = LAB_SCALE * lab[NPIX + pix];
        float f5 = LAB_SCALE * lab[2*NPIX + pix];
        outPF[pix]          = f0;
        outPF[NPIX+pix]     = f1;
        outPF[2*NPIX+pix]   = f2;
        outPF[3*NPIX+pix]   = f3;
        outPF[4*NPIX+pix]   = f4;
        outPF[5*NPIX+pix]   = f5;
        gp[p]          = f0;
        gp[CMAX+p]     = f1;
        gp[2*CMAX+p]   = f2;
        gp[3*CMAX+p]   = f3;
        gp[4*CMAX+p]   = f4;
        gp[5*CMAX+p]   = f5;
        s0+=f0; s1+=f1; s2+=f2; s3+=f3; s4+=f4; s5+=f5;
    }
    __shared__ float red[6][8];
    int wid = tid >> 5, lane = tid & 31;
    float sv[6] = {s0,s1,s2,s3,s4,s5};
#pragma unroll
    for (int c = 0; c < 6; c++){
        float v = warpSum(sv[c]);
        if (lane == 0) red[c][wid] = v;
    }
    __syncthreads();
    if (tid < 6){
        float v = 0.f;
#pragma unroll
        for (int w = 0; w < 8; w++) v += red[tid][w];
        g_spFeat[k*6 + tid] = v / (float)P;
    }
}

// ---------------- kernel 2: two-phase fused assoc + accumulate ----------------
__global__ void __launch_bounds__(EM_THREADS, 2) em_kernel(){
    extern __shared__ float sA[];   // [27][SP_]
    int k = blockIdx.x, tid = threadIdx.x;
    int kl, kh, kw, y0, ch;
    cellGeom(k, kl, kh, kw, y0, ch);
    int P = 56 * ch;

    __shared__ float sB[27*8];
    fillNbr(tid, kl, kh, kw, sB, 0);
    unsigned vmask = validMask(kl, kh, kw);
    __syncthreads();

    const float* gp = &g_pF[(size_t)k*6*CMAX];

    // ---- Phase A: per-pixel softmax -> sA ----
#pragma unroll 1
    for (int p = tid; p < P; p += EM_THREADS){
        float f0 = gp[p],        f1 = gp[CMAX+p],   f2 = gp[2*CMAX+p];
        float f3 = gp[3*CMAX+p], f4 = gp[4*CMAX+p], f5 = gp[5*CMAX+p];
        float a[27];
        pixelAssoc(sB, vmask, f0, f1, f2, f3, f4, f5, a);
#pragma unroll
        for (int j = 0; j < 27; j++) sA[j*SP_ + p] = a[j];
    }
    __syncthreads();

    // ---- Phase B: warp handles j and j+16; acc[14] in registers ----
    int wid = tid >> 5, lane = tid & 31;
    int j1 = wid, j2 = wid + 16;
    bool has2 = (j2 < 27);
    const float* a1row = &sA[j1*SP_];
    const float* a2row = &sA[(has2 ? j2 : j1)*SP_];
    float acc[14];
#pragma unroll
    for (int c = 0; c < 14; c++) acc[c] = 0.f;
#pragma unroll 1
    for (int p = lane; p < P; p += 32){
        float a1 = a1row[p];
        float a2 = has2 ? a2row[p] : 0.0f;
        float f0 = gp[p],        f1 = gp[CMAX+p],   f2 = gp[2*CMAX+p];
        float f3 = gp[3*CMAX+p], f4 = gp[4*CMAX+p], f5 = gp[5*CMAX+p];
        acc[0] = fmaf(a1, f0, acc[0]);
        acc[1] = fmaf(a1, f1, acc[1]);
        acc[2] = fmaf(a1, f2, acc[2]);
        acc[3] = fmaf(a1, f3, acc[3]);
        acc[4] = fmaf(a1, f4, acc[4]);
        acc[5] = fmaf(a1, f5, acc[5]);
        acc[6] += a1;
        acc[7]  = fmaf(a2, f0, acc[7]);
        acc[8]  = fmaf(a2, f1, acc[8]);
        acc[9]  = fmaf(a2, f2, acc[9]);
        acc[10] = fmaf(a2, f3, acc[10]);
        acc[11] = fmaf(a2, f4, acc[11]);
        acc[12] = fmaf(a2, f5, acc[12]);
        acc[13] += a2;
    }
#pragma unroll
    for (int c = 0; c < 7; c++){
        float v = warpSum(acc[c]);
        if (lane == 0) g_part[k*189 + j1*7 + c] = v;
    }
    if (has2){
#pragma unroll
        for (int c = 0; c < 7; c++){
            float v = warpSum(acc[7+c]);
            if (lane == 0) g_part[k*189 + j2*7 + c] = v;
        }
    }
}

// ---------------- kernel 3: gather partials -> normalized spFeat ----------------
__global__ void norm_kernel(){
    int k = blockIdx.x, lane = threadIdx.x;  // 32 threads, lanes 0..6 used
    int kl, kh, kw, y0, ch;
    cellGeom(k, kl, kh, kw, y0, ch);
    float v = 0.f;
    if (lane < 7){
#pragma unroll
        for (int j = 0; j < 27; j++){
            int dl = j/9 - 1, dh = (j/3)%3 - 1, dw = j%3 - 1;
            int bl = kl - dl, bh = kh - dh, bw = kw - dw;
            if ((unsigned)bl < (unsigned)KL_ &&
                (unsigned)bh < (unsigned)KH_ &&
                (unsigned)bw < (unsigned)KW_){
                int b = (bl*KH_ + bh)*KW_ + bw;
                v += g_part[b*189 + j*7 + lane];
            }
        }
    }
    float w = __shfl_sync(0xffffffffu, v, 6);
    if (lane < 6) g_spFeat[k*6 + lane] = v / fmaxf(w, 1e-12f);
}

// ---------------- kernel 4: final assoc + argmax + outputs ----------------
__global__ void __launch_bounds__(256) final_kernel(float* __restrict__ outA,
                                                    float* __restrict__ outF){
    int k = blockIdx.x, tid = threadIdx.x;
    int kl, kh, kw, y0, ch;
    cellGeom(k, kl, kh, kw, y0, ch);
    int P = 56 * ch;

    __shared__ float sB[27*8];
    __shared__ int   sNk[27];
    fillNbr(tid, kl, kh, kw, sB, sNk);
    unsigned vmask = validMask(kl, kh, kw);
    __syncthreads();

    const float* gp = &g_pF[(size_t)k*6*CMAX];
#pragma unroll 1
    for (int p = tid; p < P; p += 256){
        int lx = p % 14, q = p / 14, ly = q % ch, lt = q / ch;
        int t = 4*kl + lt, y = y0 + ly, x = 14*kw + lx;
        int pix = t*HW_ + y*W_ + x;

        float f0 = gp[p],        f1 = gp[CMAX+p],   f2 = gp[2*CMAX+p];
        float f3 = gp[3*CMAX+p], f4 = gp[4*CMAX+p], f5 = gp[5*CMAX+p];
        float a[27];
        pixelAssoc(sB, vmask, f0, f1, f2, f3, f4, f5, a);

        float best = -1.f; int bj = 0;
#pragma unroll
        for (int j = 0; j < 27; j++){
            outA[(size_t)j*NPIX + pix] = a[j];
            if (a[j] > best){ best = a[j]; bj = j; }
        }
        outF[pix] = (float)sNk[bj];
    }
}

// ---------------- kernel 5: spFeat output (transposed to [c][k]) ----------------
__global__ void spout_kernel(float* __restrict__ outSP){
    int i = blockIdx.x * blockDim.x + threadIdx.x;
    if (i < 6*K_){
        int c = i / K_, k = i - c*K_;
        outSP[i] = g_spFeat[k*6 + c];
    }
}

// ---------------- launcher ----------------
extern "C" void kernel_launch(void* const* d_in, const int* in_sizes, int n_in,
                              void* d_out, int out_size){
    const float* lab = (const float*)d_in[0];
    if (n_in > 1 && in_sizes[0] != 3*NPIX) lab = (const float*)d_in[1];

    float* out   = (float*)d_out;
    float* outPF = out;                          // 6*N   = 5505024
    float* outSP = out + (size_t)6*NPIX;         // 6*K   = 6912
    float* outA  = outSP + 6*K_;                 // 27*N  = 24772608
    float* outF  = outA + (size_t)27*NPIX;       // N     = 917504

    cudaFuncSetAttribute(em_kernel, cudaFuncAttributeMaxDynamicSharedMemorySize, EM_SMEM);

    pa_kernel<<<K_, 256>>>(lab, outPF);
    for (int it = 0; it < 4; it++){
        em_kernel<<<K_, EM_THREADS, EM_SMEM>>>();
        norm_kernel<<<K_, 32>>>();
    }
    final_kernel<<<K_, 256>>>(outA, outF);
    spout_kernel<<<27, 256>>>(outSP);            // 6912 = 27*256
}

// round 6
// speedup vs baseline: 1.4764x; 1.2419x over previous
#include <cuda_runtime.h>

// ---------------- problem constants ----------------
#define L_   8
#define H_   256
#define W_   448
#define KL_  2
#define KH_  18
#define KW_  32
#define K_   1152              // KL*KH*KW
#define HW_  (H_*W_)           // 114688
#define NPIX (L_*HW_)          // 917504
#define CMAX 840               // max pixels per cell: 4 * 15 * 14

#define T_SCALE   0.625f                       // Kl/(0.4*L)
#define YX_SCALE  ((float)0.17857142857142858) // max(Kh/(0.4*H), Kw/(0.4*W))
#define LAB_SCALE 0.26f

#define EM_THREADS 512
// dynamic smem: sA[27][840] + sF[6][840]
#define EM_SMEM    (33 * CMAX * (int)sizeof(float))   // 110880 bytes

// ---------------- device scratch (no allocs allowed) ----------------
__device__ float  g_pF[K_*6*CMAX];     // cell-blocked pixel features [k][c][p] (~23MB)
__device__ float  g_spFeat[K_*6];      // superpixel features [k][c]
__device__ float  g_part[K_*189];      // per-block partial sums [k][j*7+c] (c=6 -> weight)
__device__ float4 g_sB4[K_*27*2];      // per-cell neighbor coeffs: {-2sp[0..3]},{-2sp[4..5],|sp|^2,nk}

__device__ __forceinline__ float warpSum(float v){
#pragma unroll
    for (int o = 16; o > 0; o >>= 1) v += __shfl_down_sync(0xffffffffu, v, o);
    return v;
}

// fast exp for u <= 0, FMA-pipe only (no MUFU). rel err ~2.4e-6.
__device__ __forceinline__ float fastExpNeg(float u){
    float y = fmaxf(u * 1.44269504f, -126.0f);
    float r = rintf(y);
    float f = y - r;
    float p = 1.33336498e-3f;
    p = fmaf(p, f, 9.61817007e-3f);
    p = fmaf(p, f, 5.55041087e-2f);
    p = fmaf(p, f, 2.40226507e-1f);
    p = fmaf(p, f, 6.93147182e-1f);
    p = fmaf(p, f, 1.0f);
    int n = (int)r;
    return p * __int_as_float((n + 127) << 23);
}

// cell geometry: t in [4kl,4kl+4), y in [y0,y0+ch), x in [14kw,14kw+14)
__device__ __forceinline__ void cellGeom(int k, int& kl, int& kh, int& kw, int& y0, int& ch){
    kl = k / (KH_*KW_);
    kh = (k / KW_) % KH_;
    kw = k % KW_;
    y0 = (256*kh + 17) / 18;
    int y1 = (256*(kh+1) + 17) / 18;
    ch = y1 - y0;  // 14 or 15
}

__device__ __forceinline__ unsigned validMask(int kl, int kh, int kw){
    unsigned vmask = 0;
#pragma unroll
    for (int j = 0; j < 27; j++){
        int dl = j/9 - 1, dh = (j/3)%3 - 1, dw = j%3 - 1;
        if ((unsigned)(kl+dl) < (unsigned)KL_ &&
            (unsigned)(kh+dh) < (unsigned)KH_ &&
            (unsigned)(kw+dw) < (unsigned)KW_) vmask |= (1u << j);
    }
    return vmask;
}

// fill sB[27][8]: [0..5] = -2*sp_c, [6] = |sp|^2, [7] pad. tid<27 threads.
__device__ __forceinline__ void fillNbr(int tid, int kl, int kh, int kw, float* sB){
    if (tid < 27){
        int dl = tid/9 - 1, dh = (tid/3)%3 - 1, dw = tid%3 - 1;
        int nl = min(max(kl+dl, 0), KL_-1);
        int nh = min(max(kh+dh, 0), KH_-1);
        int nw = min(max(kw+dw, 0), KW_-1);
        int nk = (nl*KH_ + nh)*KW_ + nw;
        float b = 0.f;
#pragma unroll
        for (int c = 0; c < 6; c++){
            float s = g_spFeat[nk*6 + c];
            sB[tid*8 + c] = -2.0f * s;
            b = fmaf(s, s, b);
        }
        sB[tid*8 + 6] = b;
        sB[tid*8 + 7] = 0.f;
    }
}

// ---------------- kernel 1: pFeat + blocked copy + sp_init mean ----------------
__global__ void __launch_bounds__(256) pa_kernel(const float* __restrict__ lab,
                                                 float* __restrict__ outPF){
    int k = blockIdx.x, tid = threadIdx.x;
    int kl, kh, kw, y0, ch;
    cellGeom(k, kl, kh, kw, y0, ch);
    int P = 56 * ch;  // 4 * ch * 14

    float s0=0.f,s1=0.f,s2=0.f,s3=0.f,s4=0.f,s5=0.f;
    float* gp = &g_pF[(size_t)k*6*CMAX];
#pragma unroll 1
    for (int p = tid; p < P; p += 256){
        int lx = p % 14, q = p / 14, ly = q % ch, lt = q / ch;
        int t = 4*kl + lt, y = y0 + ly, x = 14*kw + lx;
        int pix = t*HW_ + y*W_ + x;
        float f0 = T_SCALE  * (float)t;
        float f1 = YX_SCALE * (float)y;
        float f2 = YX_SCALE * (float)x;
        float f3 = LAB_SCALE * lab[pix];
        float f4 = LAB_SCALE * lab[NPIX + pix];
        float f5 = LAB_SCALE * lab[2*NPIX + pix];
        outPF[pix]          = f0;
        outPF[NPIX+pix]     = f1;
        outPF[2*NPIX+pix]   = f2;
        outPF[3*NPIX+pix]   = f3;
        outPF[4*NPIX+pix]   = f4;
        outPF[5*NPIX+pix]   = f5;
        gp[p]          = f0;
        gp[CMAX+p]     = f1;
        gp[2*CMAX+p]   = f2;
        gp[3*CMAX+p]   = f3;
        gp[4*CMAX+p]   = f4;
        gp[5*CMAX+p]   = f5;
        s0+=f0; s1+=f1; s2+=f2; s3+=f3; s4+=f4; s5+=f5;
    }
    __shared__ float red[6][8];
    int wid = tid >> 5, lane = tid & 31;
    float sv[6] = {s0,s1,s2,s3,s4,s5};
#pragma unroll
    for (int c = 0; c < 6; c++){
        float v = warpSum(sv[c]);
        if (lane == 0) red[c][wid] = v;
    }
    __syncthreads();
    if (tid < 6){
        float v = 0.f;
#pragma unroll
        for (int w = 0; w < 8; w++) v += red[tid][w];
        g_spFeat[k*6 + tid] = v / (float)P;
    }
}

// ---------------- kernel 2: two-phase fused assoc + accumulate (SMEM-resident) ----
__global__ void __launch_bounds__(EM_THREADS, 2) em_kernel(){
    extern __shared__ float smem[];     // sA[27*840] | sF[6*840]
    float* sA = smem;
    float* sF = smem + 27*CMAX;
    int k = blockIdx.x, tid = threadIdx.x;
    int kl, kh, kw, y0, ch;
    cellGeom(k, kl, kh, kw, y0, ch);
    int P = 56 * ch;

    __shared__ float sB[27*8];
    fillNbr(tid, kl, kh, kw, sB);
    unsigned vmask = validMask(kl, kh, kw);

    // cooperative copy of this block's feature slab (contiguous 6*CMAX floats)
    const float4* gp4 = (const float4*)&g_pF[(size_t)k*6*CMAX];
    float4* sF4 = (float4*)sF;
#pragma unroll 1
    for (int i = tid; i < 6*CMAX/4; i += EM_THREADS) sF4[i] = gp4[i];
    __syncthreads();

    // ---- Phase A: per-pixel softmax -> sA ----
#pragma unroll 1
    for (int p = tid; p < P; p += EM_THREADS){
        float f0 = sF[p],        f1 = sF[CMAX+p],   f2 = sF[2*CMAX+p];
        float f3 = sF[3*CMAX+p], f4 = sF[4*CMAX+p], f5 = sF[5*CMAX+p];
        float e[27];
#pragma unroll
        for (int j = 0; j < 27; j++){
            float4 b0 = *(const float4*)&sB[j*8];
            float4 b1 = *(const float4*)&sB[j*8 + 4];
            float dd = b1.z;
            dd = fmaf(f0, b0.x, dd);
            dd = fmaf(f1, b0.y, dd);
            dd = fmaf(f2, b0.z, dd);
            dd = fmaf(f3, b0.w, dd);
            dd = fmaf(f4, b1.x, dd);
            dd = fmaf(f5, b1.y, dd);
            e[j] = (vmask & (1u << j)) ? dd : 1e30f;
        }
        float m = e[0];
#pragma unroll
        for (int j = 1; j < 27; j++) m = fminf(m, e[j]);
        float sum = 0.f;
#pragma unroll
        for (int j = 0; j < 27; j++){
            float v = fastExpNeg(m - e[j]);
            v = (vmask & (1u << j)) ? v : 0.0f;
            e[j] = v; sum += v;
        }
        float r = 1.0f / sum;
#pragma unroll
        for (int j = 0; j < 27; j++) sA[j*CMAX + p] = e[j] * r;
    }
    __syncthreads();

    // ---- Phase B: warp handles j and j+16; all operands in SMEM ----
    int wid = tid >> 5, lane = tid & 31;
    int j1 = wid, j2 = wid + 16;
    bool has2 = (j2 < 27);
    const float* a1row = &sA[j1*CMAX];
    const float* a2row = &sA[(has2 ? j2 : j1)*CMAX];
    float acc[14];
#pragma unroll
    for (int c = 0; c < 14; c++) acc[c] = 0.f;
#pragma unroll 1
    for (int p = lane; p < P; p += 32){
        float a1 = a1row[p];
        float a2 = has2 ? a2row[p] : 0.0f;
        float f0 = sF[p],        f1 = sF[CMAX+p],   f2 = sF[2*CMAX+p];
        float f3 = sF[3*CMAX+p], f4 = sF[4*CMAX+p], f5 = sF[5*CMAX+p];
        acc[0] = fmaf(a1, f0, acc[0]);
        acc[1] = fmaf(a1, f1, acc[1]);
        acc[2] = fmaf(a1, f2, acc[2]);
        acc[3] = fmaf(a1, f3, acc[3]);
        acc[4] = fmaf(a1, f4, acc[4]);
        acc[5] = fmaf(a1, f5, acc[5]);
        acc[6] += a1;
        acc[7]  = fmaf(a2, f0, acc[7]);
        acc[8]  = fmaf(a2, f1, acc[8]);
        acc[9]  = fmaf(a2, f2, acc[9]);
        acc[10] = fmaf(a2, f3, acc[10]);
        acc[11] = fmaf(a2, f4, acc[11]);
        acc[12] = fmaf(a2, f5, acc[12]);
        acc[13] += a2;
    }
#pragma unroll
    for (int c = 0; c < 7; c++){
        float v = warpSum(acc[c]);
        if (lane == 0) g_part[k*189 + j1*7 + c] = v;
    }
    if (has2){
#pragma unroll
        for (int c = 0; c < 7; c++){
            float v = warpSum(acc[7+c]);
            if (lane == 0) g_part[k*189 + j2*7 + c] = v;
        }
    }
}

// ---------------- kernel 3: gather partials -> normalized spFeat ----------------
__global__ void norm_kernel(){
    int k = blockIdx.x, lane = threadIdx.x;  // 32 threads, lanes 0..6 used
    int kl, kh, kw, y0, ch;
    cellGeom(k, kl, kh, kw, y0, ch);
    float v = 0.f;
    if (lane < 7){
#pragma unroll
        for (int j = 0; j < 27; j++){
            int dl = j/9 - 1, dh = (j/3)%3 - 1, dw = j%3 - 1;
            int bl = kl - dl, bh = kh - dh, bw = kw - dw;
            if ((unsigned)bl < (unsigned)KL_ &&
                (unsigned)bh < (unsigned)KH_ &&
                (unsigned)bw < (unsigned)KW_){
                int b = (bl*KH_ + bh)*KW_ + bw;
                v += g_part[b*189 + j*7 + lane];
            }
        }
    }
    float w = __shfl_sync(0xffffffffu, v, 6);
    if (lane < 6) g_spFeat[k*6 + lane] = v / fmaxf(w, 1e-12f);
}

// ---------------- kernel 3b: precompute per-cell neighbor coeff table ----------------
__global__ void spB_kernel(){
    int k = blockIdx.x, j = threadIdx.x;
    if (j >= 27) return;
    int kl = k / (KH_*KW_), kh = (k / KW_) % KH_, kw = k % KW_;
    int dl = j/9 - 1, dh = (j/3)%3 - 1, dw = j%3 - 1;
    int nl = min(max(kl+dl, 0), KL_-1);
    int nh = min(max(kh+dh, 0), KH_-1);
    int nw = min(max(kw+dw, 0), KW_-1);
    int nk = (nl*KH_ + nh)*KW_ + nw;
    float s[6]; float b = 0.f;
#pragma unroll
    for (int c = 0; c < 6; c++){ s[c] = g_spFeat[nk*6 + c]; b = fmaf(s[c], s[c], b); }
    float4 v0 = make_float4(-2.f*s[0], -2.f*s[1], -2.f*s[2], -2.f*s[3]);
    float4 v1 = make_float4(-2.f*s[4], -2.f*s[5], b, (float)nk);
    g_sB4[(k*27 + j)*2]     = v0;
    g_sB4[(k*27 + j)*2 + 1] = v1;
}

// ---------------- kernel 4: final assoc + argmax, global-pixel coalesced ----------------
__global__ void __launch_bounds__(256) final_kernel(const float* __restrict__ outPF,
                                                    float* __restrict__ outA,
                                                    float* __restrict__ outF){
    int pix = blockIdx.x * 256 + threadIdx.x;   // grid = NPIX/256
    int t = pix / HW_; int rr = pix - t*HW_;
    int y = rr / W_;   int x  = rr - y*W_;
    int kl = t >> 2;
    int kh = (y * 18) >> 8;
    int kw = x / 14;
    int k  = (kl*KH_ + kh)*KW_ + kw;
    unsigned vmask = validMask(kl, kh, kw);

    float f0 = outPF[pix];
    float f1 = outPF[NPIX + pix];
    float f2 = outPF[2*NPIX + pix];
    float f3 = outPF[3*NPIX + pix];
    float f4 = outPF[4*NPIX + pix];
    float f5 = outPF[5*NPIX + pix];

    float e[27]; float nkf[27];
#pragma unroll
    for (int j = 0; j < 27; j++){
        float4 b0 = __ldg(&g_sB4[(k*27 + j)*2]);
        float4 b1 = __ldg(&g_sB4[(k*27 + j)*2 + 1]);
        float dd = b1.z;
        dd = fmaf(f0, b0.x, dd);
        dd = fmaf(f1, b0.y, dd);
        dd = fmaf(f2, b0.z, dd);
        dd = fmaf(f3, b0.w, dd);
        dd = fmaf(f4, b1.x, dd);
        dd = fmaf(f5, b1.y, dd);
        e[j] = (vmask & (1u << j)) ? dd : 1e30f;
        nkf[j] = b1.w;
    }
    float m = e[0];
#pragma unroll
    for (int j = 1; j < 27; j++) m = fminf(m, e[j]);
    float sum = 0.f;
#pragma unroll
    for (int j = 0; j < 27; j++){
        float v = fastExpNeg(m - e[j]);
        v = (vmask & (1u << j)) ? v : 0.0f;
        e[j] = v; sum += v;
    }
    float r = 1.0f / sum;
    float best = -1.f; float bnk = 0.f;
#pragma unroll
    for (int j = 0; j < 27; j++){
        float a = e[j] * r;
        outA[(size_t)j*NPIX + pix] = a;
        if (a > best){ best = a; bnk = nkf[j]; }
    }
    outF[pix] = bnk;
}

// ---------------- kernel 5: spFeat output (transposed to [c][k]) ----------------
__global__ void spout_kernel(float* __restrict__ outSP){
    int i = blockIdx.x * blockDim.x + threadIdx.x;
    if (i < 6*K_){
        int c = i / K_, k = i - c*K_;
        outSP[i] = g_spFeat[k*6 + c];
    }
}

// ---------------- launcher ----------------
extern "C" void kernel_launch(void* const* d_in, const int* in_sizes, int n_in,
                              void* d_out, int out_size){
    const float* lab = (const float*)d_in[0];
    if (n_in > 1 && in_sizes[0] != 3*NPIX) lab = (const float*)d_in[1];

    float* out   = (float*)d_out;
    float* outPF = out;                          // 6*N   = 5505024
    float* outSP = out + (size_t)6*NPIX;         // 6*K   = 6912
    float* outA  = outSP + 6*K_;                 // 27*N  = 24772608
    float* outF  = outA + (size_t)27*NPIX;       // N     = 917504

    cudaFuncSetAttribute(em_kernel, cudaFuncAttributeMaxDynamicSharedMemorySize, EM_SMEM);

    pa_kernel<<<K_, 256>>>(lab, outPF);
    for (int it = 0; it < 4; it++){
        em_kernel<<<K_, EM_THREADS, EM_SMEM>>>();
        norm_kernel<<<K_, 32>>>();
    }
    spB_kernel<<<K_, 32>>>();
    final_kernel<<<NPIX/256, 256>>>(outPF, outA, outF);
    spout_kernel<<<27, 256>>>(outSP);            // 6912 = 27*256
}

// round 7
// speedup vs baseline: 1.5504x; 1.0502x over previous
#include <cuda_runtime.h>

// ---------------- problem constants ----------------
#define L_   8
#define H_   256
#define W_   448
#define KL_  2
#define KH_  18
#define KW_  32
#define K_   1152              // KL*KH*KW
#define HW_  (H_*W_)           // 114688
#define NPIX (L_*HW_)          // 917504
#define CMAX 840               // max pixels per cell: 4 * 15 * 14

#define T_SCALE   0.625f                       // Kl/(0.4*L)
#define YX_SCALE  ((float)0.17857142857142858) // max(Kh/(0.4*H), Kw/(0.4*W))
#define LAB_SCALE 0.26f

#define EM_THREADS 512
// dynamic smem: sA[27][840] + sF[6][840]
#define EM_SMEM    (33 * CMAX * (int)sizeof(float))   // 110880 bytes

// ---------------- device scratch (no allocs allowed) ----------------
__device__ float  g_pF[K_*6*CMAX];     // cell-blocked pixel features [k][c][p] (~23MB)
__device__ float  g_spFeat[K_*6];      // superpixel features [k][c]
__device__ float  g_part[K_*189];      // per-block partial sums [k][j*7+c] (c=6 -> weight)
__device__ float4 g_sB4[K_*27*2];      // per-cell neighbor coeffs: {-2sp[0..3]},{-2sp[4..5],|sp|^2,nk}

__device__ __forceinline__ float warpSum(float v){
#pragma unroll
    for (int o = 16; o > 0; o >>= 1) v += __shfl_down_sync(0xffffffffu, v, o);
    return v;
}

// fast exp, FMA-pipe only (no MUFU), two-sided clamp. rel err ~2.4e-6.
__device__ __forceinline__ float fastExp(float u){
    float y = fminf(fmaxf(u * 1.44269504f, -126.0f), 126.0f);
    float r = rintf(y);
    float f = y - r;
    float p = 1.33336498e-3f;
    p = fmaf(p, f, 9.61817007e-3f);
    p = fmaf(p, f, 5.55041087e-2f);
    p = fmaf(p, f, 2.40226507e-1f);
    p = fmaf(p, f, 6.93147182e-1f);
    p = fmaf(p, f, 1.0f);
    int n = (int)r;
    return p * __int_as_float((n + 127) << 23);
}

// cell geometry: t in [4kl,4kl+4), y in [y0,y0+ch), x in [14kw,14kw+14)
__device__ __forceinline__ void cellGeom(int k, int& kl, int& kh, int& kw, int& y0, int& ch){
    kl = k / (KH_*KW_);
    kh = (k / KW_) % KH_;
    kw = k % KW_;
    y0 = (256*kh + 17) / 18;
    int y1 = (256*(kh+1) + 17) / 18;
    ch = y1 - y0;  // 14 or 15
}

__device__ __forceinline__ unsigned validMask(int kl, int kh, int kw){
    unsigned vmask = 0;
#pragma unroll
    for (int j = 0; j < 27; j++){
        int dl = j/9 - 1, dh = (j/3)%3 - 1, dw = j%3 - 1;
        if ((unsigned)(kl+dl) < (unsigned)KL_ &&
            (unsigned)(kh+dh) < (unsigned)KH_ &&
            (unsigned)(kw+dw) < (unsigned)KW_) vmask |= (1u << j);
    }
    return vmask;
}

// fill sB[27][8]: [0..5] = -2*sp_c, [6] = |sp|^2, [7] pad. tid<27 threads.
__device__ __forceinline__ void fillNbr(int tid, int kl, int kh, int kw, float* sB){
    if (tid < 27){
        int dl = tid/9 - 1, dh = (tid/3)%3 - 1, dw = tid%3 - 1;
        int nl = min(max(kl+dl, 0), KL_-1);
        int nh = min(max(kh+dh, 0), KH_-1);
        int nw = min(max(kw+dw, 0), KW_-1);
        int nk = (nl*KH_ + nh)*KW_ + nw;
        float b = 0.f;
#pragma unroll
        for (int c = 0; c < 6; c++){
            float s = g_spFeat[nk*6 + c];
            sB[tid*8 + c] = -2.0f * s;
            b = fmaf(s, s, b);
        }
        sB[tid*8 + 6] = b;
        sB[tid*8 + 7] = 0.f;
    }
}

// ---------------- kernel 1: pFeat + blocked copy + sp_init mean ----------------
__global__ void __launch_bounds__(256) pa_kernel(const float* __restrict__ lab,
                                                 float* __restrict__ outPF){
    int k = blockIdx.x, tid = threadIdx.x;
    int kl, kh, kw, y0, ch;
    cellGeom(k, kl, kh, kw, y0, ch);
    int P = 56 * ch;  // 4 * ch * 14

    float s0=0.f,s1=0.f,s2=0.f,s3=0.f,s4=0.f,s5=0.f;
    float* gp = &g_pF[(size_t)k*6*CMAX];
#pragma unroll 1
    for (int p = tid; p < P; p += 256){
        int lx = p % 14, q = p / 14, ly = q % ch, lt = q / ch;
        int t = 4*kl + lt, y = y0 + ly, x = 14*kw + lx;
        int pix = t*HW_ + y*W_ + x;
        float f0 = T_SCALE  * (float)t;
        float f1 = YX_SCALE * (float)y;
        float f2 = YX_SCALE * (float)x;
        float f3 = LAB_SCALE * lab[pix];
        float f4 = LAB_SCALE * lab[NPIX + pix];
        float f5 = LAB_SCALE * lab[2*NPIX + pix];
        outPF[pix]          = f0;
        outPF[NPIX+pix]     = f1;
        outPF[2*NPIX+pix]   = f2;
        outPF[3*NPIX+pix]   = f3;
        outPF[4*NPIX+pix]   = f4;
        outPF[5*NPIX+pix]   = f5;
        gp[p]          = f0;
        gp[CMAX+p]     = f1;
        gp[2*CMAX+p]   = f2;
        gp[3*CMAX+p]   = f3;
        gp[4*CMAX+p]   = f4;
        gp[5*CMAX+p]   = f5;
        s0+=f0; s1+=f1; s2+=f2; s3+=f3; s4+=f4; s5+=f5;
    }
    __shared__ float red[6][8];
    int wid = tid >> 5, lane = tid & 31;
    float sv[6] = {s0,s1,s2,s3,s4,s5};
#pragma unroll
    for (int c = 0; c < 6; c++){
        float v = warpSum(sv[c]);
        if (lane == 0) red[c][wid] = v;
    }
    __syncthreads();
    if (tid < 6){
        float v = 0.f;
#pragma unroll
        for (int w = 0; w < 8; w++) v += red[tid][w];
        g_spFeat[k*6 + tid] = v / (float)P;
    }
}

// ---------------- kernel 2: two-phase fused assoc + accumulate (SMEM, spill-free) ----
__global__ void __launch_bounds__(EM_THREADS, 2) em_kernel(){
    extern __shared__ float smem[];     // sA[27*840] | sF[6*840]
    float* sA = smem;
    float* sF = smem + 27*CMAX;
    int k = blockIdx.x, tid = threadIdx.x;
    int kl, kh, kw, y0, ch;
    cellGeom(k, kl, kh, kw, y0, ch);
    int P = 56 * ch;

    __shared__ float sB[27*8];
    fillNbr(tid, kl, kh, kw, sB);
    unsigned vmask = validMask(kl, kh, kw);

    // cooperative copy of this block's feature slab (contiguous 6*CMAX floats)
    const float4* gp4 = (const float4*)&g_pF[(size_t)k*6*CMAX];
    float4* sF4 = (float4*)sF;
#pragma unroll 1
    for (int i = tid; i < 6*CMAX/4; i += EM_THREADS) sF4[i] = gp4[i];
    __syncthreads();

    // ---- Phase A: per-pixel softmax -> sA (no register arrays, no min chain) ----
#pragma unroll 1
    for (int p = tid; p < P; p += EM_THREADS){
        float f0 = sF[p],        f1 = sF[CMAX+p],   f2 = sF[2*CMAX+p];
        float f3 = sF[3*CMAX+p], f4 = sF[4*CMAX+p], f5 = sF[5*CMAX+p];
        // shift = distance to own (center, j=13) cell: >= min_j d_j, small, always valid
        float4 c0 = *(const float4*)&sB[13*8];
        float4 c1 = *(const float4*)&sB[13*8 + 4];
        float shift = c1.z;
        shift = fmaf(f0, c0.x, shift);
        shift = fmaf(f1, c0.y, shift);
        shift = fmaf(f2, c0.z, shift);
        shift = fmaf(f3, c0.w, shift);
        shift = fmaf(f4, c1.x, shift);
        shift = fmaf(f5, c1.y, shift);

        float sum = 0.f;
#pragma unroll
        for (int j = 0; j < 27; j++){
            float4 b0 = *(const float4*)&sB[j*8];
            float4 b1 = *(const float4*)&sB[j*8 + 4];
            float dd = b1.z;
            dd = fmaf(f0, b0.x, dd);
            dd = fmaf(f1, b0.y, dd);
            dd = fmaf(f2, b0.z, dd);
            dd = fmaf(f3, b0.w, dd);
            dd = fmaf(f4, b1.x, dd);
            dd = fmaf(f5, b1.y, dd);
            float v = fastExp(shift - dd);
            v = (vmask & (1u << j)) ? v : 0.0f;
            sA[j*CMAX + p] = v;
            sum += v;
        }
        float r = 1.0f / sum;    // sum >= 1 (center term is exp(0)=1)
#pragma unroll
        for (int j = 0; j < 27; j++) sA[j*CMAX + p] *= r;
    }
    __syncthreads();

    // ---- Phase B: warp handles j and j+16; all operands in SMEM ----
    int wid = tid >> 5, lane = tid & 31;
    int j1 = wid, j2 = wid + 16;
    bool has2 = (j2 < 27);
    const float* a1row = &sA[j1*CMAX];
    const float* a2row = &sA[(has2 ? j2 : j1)*CMAX];
    float acc[14];
#pragma unroll
    for (int c = 0; c < 14; c++) acc[c] = 0.f;
#pragma unroll 1
    for (int p = lane; p < P; p += 32){
        float a1 = a1row[p];
        float a2 = has2 ? a2row[p] : 0.0f;
        float f0 = sF[p],        f1 = sF[CMAX+p],   f2 = sF[2*CMAX+p];
        float f3 = sF[3*CMAX+p], f4 = sF[4*CMAX+p], f5 = sF[5*CMAX+p];
        acc[0] = fmaf(a1, f0, acc[0]);
        acc[1] = fmaf(a1, f1, acc[1]);
        acc[2] = fmaf(a1, f2, acc[2]);
        acc[3] = fmaf(a1, f3, acc[3]);
        acc[4] = fmaf(a1, f4, acc[4]);
        acc[5] = fmaf(a1, f5, acc[5]);
        acc[6] += a1;
        acc[7]  = fmaf(a2, f0, acc[7]);
        acc[8]  = fmaf(a2, f1, acc[8]);
        acc[9]  = fmaf(a2, f2, acc[9]);
        acc[10] = fmaf(a2, f3, acc[10]);
        acc[11] = fmaf(a2, f4, acc[11]);
        acc[12] = fmaf(a2, f5, acc[12]);
        acc[13] += a2;
    }
#pragma unroll
    for (int c = 0; c < 7; c++){
        float v = warpSum(acc[c]);
        if (lane == 0) g_part[k*189 + j1*7 + c] = v;
    }
    if (has2){
#pragma unroll
        for (int c = 0; c < 7; c++){
            float v = warpSum(acc[7+c]);
            if (lane == 0) g_part[k*189 + j2*7 + c] = v;
        }
    }
}

// ---------------- kernel 3: gather partials -> normalized spFeat ----------------
__global__ void norm_kernel(){
    int k = blockIdx.x, lane = threadIdx.x;  // 32 threads, lanes 0..6 used
    int kl, kh, kw, y0, ch;
    cellGeom(k, kl, kh, kw, y0, ch);
    float v = 0.f;
    if (lane < 7){
#pragma unroll
        for (int j = 0; j < 27; j++){
            int dl = j/9 - 1, dh = (j/3)%3 - 1, dw = j%3 - 1;
            int bl = kl - dl, bh = kh - dh, bw = kw - dw;
            if ((unsigned)bl < (unsigned)KL_ &&
                (unsigned)bh < (unsigned)KH_ &&
                (unsigned)bw < (unsigned)KW_){
                int b = (bl*KH_ + bh)*KW_ + bw;
                v += g_part[b*189 + j*7 + lane];
            }
        }
    }
    float w = __shfl_sync(0xffffffffu, v, 6);
    if (lane < 6) g_spFeat[k*6 + lane] = v / fmaxf(w, 1e-12f);
}

// ---------------- kernel 3b: precompute per-cell neighbor coeff table ----------------
__global__ void spB_kernel(){
    int k = blockIdx.x, j = threadIdx.x;
    if (j >= 27) return;
    int kl = k / (KH_*KW_), kh = (k / KW_) % KH_, kw = k % KW_;
    int dl = j/9 - 1, dh = (j/3)%3 - 1, dw = j%3 - 1;
    int nl = min(max(kl+dl, 0), KL_-1);
    int nh = min(max(kh+dh, 0), KH_-1);
    int nw = min(max(kw+dw, 0), KW_-1);
    int nk = (nl*KH_ + nh)*KW_ + nw;
    float s[6]; float b = 0.f;
#pragma unroll
    for (int c = 0; c < 6; c++){ s[c] = g_spFeat[nk*6 + c]; b = fmaf(s[c], s[c], b); }
    float4 v0 = make_float4(-2.f*s[0], -2.f*s[1], -2.f*s[2], -2.f*s[3]);
    float4 v1 = make_float4(-2.f*s[4], -2.f*s[5], b, (float)nk);
    g_sB4[(k*27 + j)*2]     = v0;
    g_sB4[(k*27 + j)*2 + 1] = v1;
}

// ---------------- kernel 4: final assoc + argmax, global-pixel coalesced ----------------
__global__ void __launch_bounds__(256) final_kernel(const float* __restrict__ outPF,
                                                    float* __restrict__ outA,
                                                    float* __restrict__ outF){
    int pix = blockIdx.x * 256 + threadIdx.x;   // grid = NPIX/256
    int t = pix / HW_; int rr = pix - t*HW_;
    int y = rr / W_;   int x  = rr - y*W_;
    int kl = t >> 2;
    int kh = (y * 18) >> 8;
    int kw = x / 14;
    int k  = (kl*KH_ + kh)*KW_ + kw;
    unsigned vmask = validMask(kl, kh, kw);

    float f0 = outPF[pix];
    float f1 = outPF[NPIX + pix];
    float f2 = outPF[2*NPIX + pix];
    float f3 = outPF[3*NPIX + pix];
    float f4 = outPF[4*NPIX + pix];
    float f5 = outPF[5*NPIX + pix];

    // shift = center (j=13) distance
    float4 c0 = __ldg(&g_sB4[(k*27 + 13)*2]);
    float4 c1 = __ldg(&g_sB4[(k*27 + 13)*2 + 1]);
    float shift = c1.z;
    shift = fmaf(f0, c0.x, shift);
    shift = fmaf(f1, c0.y, shift);
    shift = fmaf(f2, c0.z, shift);
    shift = fmaf(f3, c0.w, shift);
    shift = fmaf(f4, c1.x, shift);
    shift = fmaf(f5, c1.y, shift);

    float e[27]; float nkf[27];
    float sum = 0.f;
#pragma unroll
    for (int j = 0; j < 27; j++){
        float4 b0 = __ldg(&g_sB4[(k*27 + j)*2]);
        float4 b1 = __ldg(&g_sB4[(k*27 + j)*2 + 1]);
        float dd = b1.z;
        dd = fmaf(f0, b0.x, dd);
        dd = fmaf(f1, b0.y, dd);
        dd = fmaf(f2, b0.z, dd);
        dd = fmaf(f3, b0.w, dd);
        dd = fmaf(f4, b1.x, dd);
        dd = fmaf(f5, b1.y, dd);
        float v = fastExp(shift - dd);
        v = (vmask & (1u << j)) ? v : 0.0f;
        e[j] = v; sum += v;
        nkf[j] = b1.w;
    }
    float r = 1.0f / sum;
    float best = -1.f; float bnk = 0.f;
#pragma unroll
    for (int j = 0; j < 27; j++){
        float a = e[j] * r;
        outA[(size_t)j*NPIX + pix] = a;
        if (a > best){ best = a; bnk = nkf[j]; }
    }
    outF[pix] = bnk;
}

// ---------------- kernel 5: spFeat output (transposed to [c][k]) ----------------
__global__ void spout_kernel(float* __restrict__ outSP){
    int i = blockIdx.x * blockDim.x + threadIdx.x;
    if (i < 6*K_){
        int c = i / K_, k = i - c*K_;
        outSP[i] = g_spFeat[k*6 + c];
    }
}

// ---------------- launcher ----------------
extern "C" void kernel_launch(void* const* d_in, const int* in_sizes, int n_in,
                              void* d_out, int out_size){
    const float* lab = (const float*)d_in[0];
    if (n_in > 1 && in_sizes[0] != 3*NPIX) lab = (const float*)d_in[1];

    float* out   = (float*)d_out;
    float* outPF = out;                          // 6*N   = 5505024
    float* outSP = out + (size_t)6*NPIX;         // 6*K   = 6912
    float* outA  = outSP + 6*K_;                 // 27*N  = 24772608
    float* outF  = outA + (size_t)27*NPIX;       // N     = 917504

    cudaFuncSetAttribute(em_kernel, cudaFuncAttributeMaxDynamicSharedMemorySize, EM_SMEM);

    pa_kernel<<<K_, 256>>>(lab, outPF);
    for (int it = 0; it < 4; it++){
        em_kernel<<<K_, EM_THREADS, EM_SMEM>>>();
        norm_kernel<<<K_, 32>>>();
    }
    spB_kernel<<<K_, 32>>>();
    final_kernel<<<NPIX/256, 256>>>(outPF, outA, outF);
    spout_kernel<<<27, 256>>>(outSP);            // 6912 = 27*256
}

// round 8
// speedup vs baseline: 3.7480x; 2.4174x over previous
#include <cuda_runtime.h>

// ---------------- problem constants ----------------
#define L_   8
#define H_   256
#define W_   448
#define KL_  2
#define KH_  18
#define KW_  32
#define K_   1152              // KL*KH*KW
#define HW_  (H_*W_)           // 114688
#define NPIX (L_*HW_)          // 917504
#define CMAX 840               // max pixels per cell: 4 * 15 * 14

#define T_SCALE   0.625f                       // Kl/(0.4*L)
#define YX_SCALE  ((float)0.17857142857142858) // max(Kh/(0.4*H), Kw/(0.4*W))
#define LAB_SCALE 0.26f

#define EM_THREADS 512
// dynamic smem: sA[27][840] + sR[840] + sF[6][840] = 34*840 floats
#define EM_SMEM    (34 * CMAX * (int)sizeof(float))   // 114240 bytes

// ---------------- device scratch (no allocs allowed) ----------------
__device__ float  g_pF[K_*6*CMAX];     // cell-blocked pixel features [k][c][p] (~23MB)
__device__ float  g_spFeat[K_*6];      // superpixel features [k][c]
__device__ float  g_part[K_*189];      // per-block partial sums [k][j*7+c] (c=6 -> weight)
__device__ float4 g_sB4[K_*27*2];      // per-cell neighbor coeffs: {-2sp[0..3]},{-2sp[4..5],|sp|^2,nk}

__device__ __forceinline__ float warpSum(float v){
#pragma unroll
    for (int o = 16; o > 0; o >>= 1) v += __shfl_down_sync(0xffffffffu, v, o);
    return v;
}

// fast exp, FMA/ALU pipes only (no MUFU, no F2I). Magic-number round-to-nearest.
// valid for arguments whose 2^x exponent fits [-126,126]; clamped below.
__device__ __forceinline__ float fastExp(float u){
    float y = fminf(fmaxf(u * 1.44269504f, -126.0f), 126.0f);
    float z = y + 12582912.0f;              // 2^23 * 1.5 : forces RN to integer
    int   n = __float_as_int(z) - 0x4B400000;
    float f = y - (z - 12582912.0f);        // f in [-0.5, 0.5]
    float p = 1.33336498e-3f;
    p = fmaf(p, f, 9.61817007e-3f);
    p = fmaf(p, f, 5.55041087e-2f);
    p = fmaf(p, f, 2.40226507e-1f);
    p = fmaf(p, f, 6.93147182e-1f);
    p = fmaf(p, f, 1.0f);
    return p * __int_as_float((n + 127) << 23);
}

// cell geometry: t in [4kl,4kl+4), y in [y0,y0+ch), x in [14kw,14kw+14)
__device__ __forceinline__ void cellGeom(int k, int& kl, int& kh, int& kw, int& y0, int& ch){
    kl = k / (KH_*KW_);
    kh = (k / KW_) % KH_;
    kw = k % KW_;
    y0 = (256*kh + 17) / 18;
    int y1 = (256*(kh+1) + 17) / 18;
    ch = y1 - y0;  // 14 or 15
}

__device__ __forceinline__ unsigned validMask(int kl, int kh, int kw){
    unsigned vmask = 0;
#pragma unroll
    for (int j = 0; j < 27; j++){
        int dl = j/9 - 1, dh = (j/3)%3 - 1, dw = j%3 - 1;
        if ((unsigned)(kl+dl) < (unsigned)KL_ &&
            (unsigned)(kh+dh) < (unsigned)KH_ &&
            (unsigned)(kw+dw) < (unsigned)KW_) vmask |= (1u << j);
    }
    return vmask;
}

// fill sB[27][8]: [0..5] = -2*sp_c, [6] = |sp|^2, [7] pad. tid<27 threads.
__device__ __forceinline__ void fillNbr(int tid, int kl, int kh, int kw, float* sB){
    if (tid < 27){
        int dl = tid/9 - 1, dh = (tid/3)%3 - 1, dw = tid%3 - 1;
        int nl = min(max(kl+dl, 0), KL_-1);
        int nh = min(max(kh+dh, 0), KH_-1);
        int nw = min(max(kw+dw, 0), KW_-1);
        int nk = (nl*KH_ + nh)*KW_ + nw;
        float b = 0.f;
#pragma unroll
        for (int c = 0; c < 6; c++){
            float s = g_spFeat[nk*6 + c];
            sB[tid*8 + c] = -2.0f * s;
            b = fmaf(s, s, b);
        }
        sB[tid*8 + 6] = b;
        sB[tid*8 + 7] = 0.f;
    }
}

// ---------------- kernel 1: pFeat + blocked copy + sp_init mean ----------------
__global__ void __launch_bounds__(256) pa_kernel(const float* __restrict__ lab,
                                                 float* __restrict__ outPF){
    int k = blockIdx.x, tid = threadIdx.x;
    int kl, kh, kw, y0, ch;
    cellGeom(k, kl, kh, kw, y0, ch);
    int P = 56 * ch;  // 4 * ch * 14

    float s0=0.f,s1=0.f,s2=0.f,s3=0.f,s4=0.f,s5=0.f;
    float* gp = &g_pF[(size_t)k*6*CMAX];
#pragma unroll 1
    for (int p = tid; p < P; p += 256){
        int lx = p % 14, q = p / 14, ly = q % ch, lt = q / ch;
        int t = 4*kl + lt, y = y0 + ly, x = 14*kw + lx;
        int pix = t*HW_ + y*W_ + x;
        float f0 = T_SCALE  * (float)t;
        float f1 = YX_SCALE * (float)y;
        float f2 = YX_SCALE * (float)x;
        float f3 = LAB_SCALE * lab[pix];
        float f4 = LAB_SCALE * lab[NPIX + pix];
        float f5 = LAB_SCALE * lab[2*NPIX + pix];
        outPF[pix]          = f0;
        outPF[NPIX+pix]     = f1;
        outPF[2*NPIX+pix]   = f2;
        outPF[3*NPIX+pix]   = f3;
        outPF[4*NPIX+pix]   = f4;
        outPF[5*NPIX+pix]   = f5;
        gp[p]          = f0;
        gp[CMAX+p]     = f1;
        gp[2*CMAX+p]   = f2;
        gp[3*CMAX+p]   = f3;
        gp[4*CMAX+p]   = f4;
        gp[5*CMAX+p]   = f5;
        s0+=f0; s1+=f1; s2+=f2; s3+=f3; s4+=f4; s5+=f5;
    }
    __shared__ float red[6][8];
    int wid = tid >> 5, lane = tid & 31;
    float sv[6] = {s0,s1,s2,s3,s4,s5};
#pragma unroll
    for (int c = 0; c < 6; c++){
        float v = warpSum(sv[c]);
        if (lane == 0) red[c][wid] = v;
    }
    __syncthreads();
    if (tid < 6){
        float v = 0.f;
#pragma unroll
        for (int w = 0; w < 8; w++) v += red[tid][w];
        g_spFeat[k*6 + tid] = v / (float)P;
    }
}

// ---------------- kernel 2: two-phase fused assoc + accumulate ----------------
// Phase A: per-pixel UNNORMALIZED exp -> sA, 1/sum -> sR (no normalize pass)
// Phase B: warp-per-j-pair dot products with r folded in -> g_part
__global__ void __launch_bounds__(EM_THREADS, 2) em_kernel(){
    extern __shared__ float smem[];     // sA[27*840] | sR[840] | sF[6*840]
    float* sA = smem;
    float* sR = smem + 27*CMAX;
    float* sF = smem + 28*CMAX;
    int k = blockIdx.x, tid = threadIdx.x;
    int kl, kh, kw, y0, ch;
    cellGeom(k, kl, kh, kw, y0, ch);
    int P = 56 * ch;

    __shared__ float sB[27*8];
    fillNbr(tid, kl, kh, kw, sB);
    unsigned vmask = validMask(kl, kh, kw);

    // cooperative copy of this block's feature slab (contiguous 6*CMAX floats)
    const float4* gp4 = (const float4*)&g_pF[(size_t)k*6*CMAX];
    float4* sF4 = (float4*)sF;
#pragma unroll 1
    for (int i = tid; i < 6*CMAX/4; i += EM_THREADS) sF4[i] = gp4[i];
    __syncthreads();

    // ---- Phase A ----
#pragma unroll 1
    for (int p = tid; p < P; p += EM_THREADS){
        float f0 = sF[p],        f1 = sF[CMAX+p],   f2 = sF[2*CMAX+p];
        float f3 = sF[3*CMAX+p], f4 = sF[4*CMAX+p], f5 = sF[5*CMAX+p];
        // shift = distance to own (center, j=13) cell: >= min_j d_j - bounded, valid
        float4 c0 = *(const float4*)&sB[13*8];
        float4 c1 = *(const float4*)&sB[13*8 + 4];
        float shift = c1.z;
        shift = fmaf(f0, c0.x, shift);
        shift = fmaf(f1, c0.y, shift);
        shift = fmaf(f2, c0.z, shift);
        shift = fmaf(f3, c0.w, shift);
        shift = fmaf(f4, c1.x, shift);
        shift = fmaf(f5, c1.y, shift);

        float sum = 0.f;
#pragma unroll 3
        for (int j = 0; j < 27; j++){
            float4 b0 = *(const float4*)&sB[j*8];
            float4 b1 = *(const float4*)&sB[j*8 + 4];
            float dd = b1.z;
            dd = fmaf(f0, b0.x, dd);
            dd = fmaf(f1, b0.y, dd);
            dd = fmaf(f2, b0.z, dd);
            dd = fmaf(f3, b0.w, dd);
            dd = fmaf(f4, b1.x, dd);
            dd = fmaf(f5, b1.y, dd);
            float v = fastExp(shift - dd);
            v = (vmask & (1u << j)) ? v : 0.0f;
            sA[j*CMAX + p] = v;
            sum += v;
        }
        sR[p] = 1.0f / sum;     // sum >= 1 (center term is exp(0)=1)
    }
    __syncthreads();

    // ---- Phase B: warp handles j and j+16; all operands in SMEM; r folded in ----
    int wid = tid >> 5, lane = tid & 31;
    int j1 = wid, j2 = wid + 16;
    bool has2 = (j2 < 27);
    const float* a1row = &sA[j1*CMAX];
    const float* a2row = &sA[(has2 ? j2 : j1)*CMAX];
    float acc[14];
#pragma unroll
    for (int c = 0; c < 14; c++) acc[c] = 0.f;
#pragma unroll 1
    for (int p = lane; p < P; p += 32){
        float r  = sR[p];
        float a1 = a1row[p] * r;
        float a2 = has2 ? (a2row[p] * r) : 0.0f;
        float f0 = sF[p],        f1 = sF[CMAX+p],   f2 = sF[2*CMAX+p];
        float f3 = sF[3*CMAX+p], f4 = sF[4*CMAX+p], f5 = sF[5*CMAX+p];
        acc[0] = fmaf(a1, f0, acc[0]);
        acc[1] = fmaf(a1, f1, acc[1]);
        acc[2] = fmaf(a1, f2, acc[2]);
        acc[3] = fmaf(a1, f3, acc[3]);
        acc[4] = fmaf(a1, f4, acc[4]);
        acc[5] = fmaf(a1, f5, acc[5]);
        acc[6] += a1;
        acc[7]  = fmaf(a2, f0, acc[7]);
        acc[8]  = fmaf(a2, f1, acc[8]);
        acc[9]  = fmaf(a2, f2, acc[9]);
        acc[10] = fmaf(a2, f3, acc[10]);
        acc[11] = fmaf(a2, f4, acc[11]);
        acc[12] = fmaf(a2, f5, acc[12]);
        acc[13] += a2;
    }
#pragma unroll
    for (int c = 0; c < 7; c++){
        float v = warpSum(acc[c]);
        if (lane == 0) g_part[k*189 + j1*7 + c] = v;
    }
    if (has2){
#pragma unroll
        for (int c = 0; c < 7; c++){
            float v = warpSum(acc[7+c]);
            if (lane == 0) g_part[k*189 + j2*7 + c] = v;
        }
    }
}

// ---------------- kernel 3: gather partials -> normalized spFeat ----------------
__global__ void norm_kernel(){
    int k = blockIdx.x, lane = threadIdx.x;  // 32 threads, lanes 0..6 used
    int kl, kh, kw, y0, ch;
    cellGeom(k, kl, kh, kw, y0, ch);
    float v = 0.f;
    if (lane < 7){
#pragma unroll
        for (int j = 0; j < 27; j++){
            int dl = j/9 - 1, dh = (j/3)%3 - 1, dw = j%3 - 1;
            int bl = kl - dl, bh = kh - dh, bw = kw - dw;
            if ((unsigned)bl < (unsigned)KL_ &&
                (unsigned)bh < (unsigned)KH_ &&
                (unsigned)bw < (unsigned)KW_){
                int b = (bl*KH_ + bh)*KW_ + bw;
                v += g_part[b*189 + j*7 + lane];
            }
        }
    }
    float w = __shfl_sync(0xffffffffu, v, 6);
    if (lane < 6) g_spFeat[k*6 + lane] = v / fmaxf(w, 1e-12f);
}

// ---------------- kernel 3b: precompute per-cell neighbor coeff table ----------------
__global__ void spB_kernel(){
    int k = blockIdx.x, j = threadIdx.x;
    if (j >= 27) return;
    int kl = k / (KH_*KW_), kh = (k / KW_) % KH_, kw = k % KW_;
    int dl = j/9 - 1, dh = (j/3)%3 - 1, dw = j%3 - 1;
    int nl = min(max(kl+dl, 0), KL_-1);
    int nh = min(max(kh+dh, 0), KH_-1);
    int nw = min(max(kw+dw, 0), KW_-1);
    int nk = (nl*KH_ + nh)*KW_ + nw;
    float s[6]; float b = 0.f;
#pragma unroll
    for (int c = 0; c < 6; c++){ s[c] = g_spFeat[nk*6 + c]; b = fmaf(s[c], s[c], b); }
    float4 v0 = make_float4(-2.f*s[0], -2.f*s[1], -2.f*s[2], -2.f*s[3]);
    float4 v1 = make_float4(-2.f*s[4], -2.f*s[5], b, (float)nk);
    g_sB4[(k*27 + j)*2]     = v0;
    g_sB4[(k*27 + j)*2 + 1] = v1;
}

// ---------------- kernel 4: final assoc + argmax, global-pixel coalesced ----------------
__global__ void __launch_bounds__(256) final_kernel(const float* __restrict__ outPF,
                                                    float* __restrict__ outA,
                                                    float* __restrict__ outF){
    int pix = blockIdx.x * 256 + threadIdx.x;   // grid = NPIX/256
    int t = pix / HW_; int rr = pix - t*HW_;
    int y = rr / W_;   int x  = rr - y*W_;
    int kl = t >> 2;
    int kh = (y * 18) >> 8;
    int kw = x / 14;
    int k  = (kl*KH_ + kh)*KW_ + kw;
    unsigned vmask = validMask(kl, kh, kw);

    float f0 = outPF[pix];
    float f1 = outPF[NPIX + pix];
    float f2 = outPF[2*NPIX + pix];
    float f3 = outPF[3*NPIX + pix];
    float f4 = outPF[4*NPIX + pix];
    float f5 = outPF[5*NPIX + pix];

    // shift = center (j=13) distance
    float4 c0 = __ldg(&g_sB4[(k*27 + 13)*2]);
    float4 c1 = __ldg(&g_sB4[(k*27 + 13)*2 + 1]);
    float shift = c1.z;
    shift = fmaf(f0, c0.x, shift);
    shift = fmaf(f1, c0.y, shift);
    shift = fmaf(f2, c0.z, shift);
    shift = fmaf(f3, c0.w, shift);
    shift = fmaf(f4, c1.x, shift);
    shift = fmaf(f5, c1.y, shift);

    float e[27]; float nkf[27];
    float sum = 0.f;
#pragma unroll
    for (int j = 0; j < 27; j++){
        float4 b0 = __ldg(&g_sB4[(k*27 + j)*2]);
        float4 b1 = __ldg(&g_sB4[(k*27 + j)*2 + 1]);
        float dd = b1.z;
        dd = fmaf(f0, b0.x, dd);
        dd = fmaf(f1, b0.y, dd);
        dd = fmaf(f2, b0.z, dd);
        dd = fmaf(f3, b0.w, dd);
        dd = fmaf(f4, b1.x, dd);
        dd = fmaf(f5, b1.y, dd);
        float v = fastExp(shift - dd);
        v = (vmask & (1u << j)) ? v : 0.0f;
        e[j] = v; sum += v;
        nkf[j] = b1.w;
    }
    float r = 1.0f / sum;
    float best = -1.f; float bnk = 0.f;
#pragma unroll
    for (int j = 0; j < 27; j++){
        float a = e[j] * r;
        outA[(size_t)j*NPIX + pix] = a;
        if (a > best){ best = a; bnk = nkf[j]; }
    }
    outF[pix] = bnk;
}

// ---------------- kernel 5: spFeat output (transposed to [c][k]) ----------------
__global__ void spout_kernel(float* __restrict__ outSP){
    int i = blockIdx.x * blockDim.x + threadIdx.x;
    if (i < 6*K_){
        int c = i / K_, k = i - c*K_;
        outSP[i] = g_spFeat[k*6 + c];
    }
}

// ---------------- launcher ----------------
extern "C" void kernel_launch(void* const* d_in, const int* in_sizes, int n_in,
                              void* d_out, int out_size){
    const float* lab = (const float*)d_in[0];
    if (n_in > 1 && in_sizes[0] != 3*NPIX) lab = (const float*)d_in[1];

    float* out   = (float*)d_out;
    float* outPF = out;                          // 6*N   = 5505024
    float* outSP = out + (size_t)6*NPIX;         // 6*K   = 6912
    float* outA  = outSP + 6*K_;                 // 27*N  = 24772608
    float* outF  = outA + (size_t)27*NPIX;       // N     = 917504

    cudaFuncSetAttribute(em_kernel, cudaFuncAttributeMaxDynamicSharedMemorySize, EM_SMEM);

    pa_kernel<<<K_, 256>>>(lab, outPF);
    for (int it = 0; it < 4; it++){
        em_kernel<<<K_, EM_THREADS, EM_SMEM>>>();
        norm_kernel<<<K_, 32>>>();
    }
    spB_kernel<<<K_, 32>>>();
    final_kernel<<<NPIX/256, 256>>>(outPF, outA, outF);
    spout_kernel<<<27, 256>>>(outSP);            // 6912 = 27*256
}